// round 10
// baseline (speedup 1.0000x reference)
#include <cuda_runtime.h>
#include <math.h>
#include <stdint.h>

#define Nn 4096
#define Dd 512
#define D3 1536
#define Ee 131072
#define MAXNB 128
#define HEADS 8
#define HD 64

// ---------------- scratch (device globals; referenced ONLY from device code) ----------------
__device__ int   g_winner[Nn * Nn];     // 0 = empty; else edge_id+1 (zero-init, self-restoring)
__device__ __align__(128) int   g_cnt[Nn];
__device__ __align__(128) int   g_cols[Nn * MAXNB];
__device__ __align__(128) float g_wts[Nn * MAXNB];
__device__ __align__(128) float g_qkv[Nn * D3];
__device__ __align__(128) float g_attn[Nn * Dd];    // written pre-rounded to tf32
__device__ __align__(128) float g_tmp[Nn * Dd];
__device__ __align__(128) float g_h1[Nn * Dd];      // exact (for residual)
__device__ __align__(128) float g_h1r[Nn * Dd];     // tf32-rounded (GEMM operand)
__device__ __align__(128) float g_xr[Nn * Dd];      // tf32-rounded x
__device__ __align__(128) float g_wqkvr[D3 * Dd];   // tf32-rounded weights
__device__ __align__(128) float g_wor[Dd * Dd];
__device__ __align__(128) float g_w1r[Dd * Dd];

// ---------------- helpers ----------------
__device__ __forceinline__ uint32_t smem_u32(const void* p) {
    uint32_t a;
    asm("{ .reg .u64 t; cvta.to.shared.u64 t, %1; cvt.u32.u64 %0, t; }" : "=r"(a) : "l"(p));
    return a;
}
__device__ __forceinline__ uint32_t f2tf(uint32_t fb) {
    uint32_t u;
    asm("cvt.rna.tf32.f32 %0, %1;" : "=r"(u) : "f"(__uint_as_float(fb)));
    return u;
}
__device__ __forceinline__ float roundtf(float f) {
    return __uint_as_float(f2tf(__float_as_uint(f)));
}
__device__ __forceinline__ void cp16cg(uint32_t dst, const void* src) {
    asm volatile("cp.async.cg.shared.global [%0], [%1], 16;" :: "r"(dst), "l"(src));
}
__device__ __forceinline__ void ldsm4(uint32_t* r, uint32_t addr) {
    asm volatile("ldmatrix.sync.aligned.m8n8.x4.shared.b16 {%0,%1,%2,%3}, [%4];"
        : "=r"(r[0]), "=r"(r[1]), "=r"(r[2]), "=r"(r[3]) : "r"(addr));
}
__device__ __forceinline__ void mma8(float* c, const uint32_t* a, const uint32_t* b) {
    asm volatile(
        "mma.sync.aligned.m16n8k8.row.col.f32.tf32.tf32.f32 "
        "{%0,%1,%2,%3},{%4,%5,%6,%7},{%8,%9},{%0,%1,%2,%3};"
        : "+f"(c[0]), "+f"(c[1]), "+f"(c[2]), "+f"(c[3])
        : "r"(a[0]), "r"(a[1]), "r"(a[2]), "r"(a[3]), "r"(b[0]), "r"(b[1]));
}

// ---------------- tf32 pre-round pass (operands already tf32 pass through mma exactly) ----------------
template<int MODE>
__global__ void k_round(const float* __restrict__ src) {
    constexpr int n4 = ((MODE == 0) ? Nn * Dd : (MODE == 1) ? D3 * Dd : Dd * Dd) / 4;
    float* dst = (MODE == 0) ? (float*)g_xr : (MODE == 1) ? (float*)g_wqkvr
               : (MODE == 2) ? (float*)g_wor : (float*)g_w1r;
    int i = blockIdx.x * 256 + threadIdx.x;
    if (i >= n4) return;
    float4 v = ((const float4*)src)[i];
    v.x = roundtf(v.x); v.y = roundtf(v.y); v.z = roundtf(v.z); v.w = roundtf(v.w);
    ((float4*)dst)[i] = v;
}

// ---------------- edge access (dtype auto-detect per-thread) ----------------
__device__ __forceinline__ bool edge_is64(const void* ei) {
    const uint32_t* w = (const uint32_t*)ei;
    return (w[1] | w[3] | w[5] | w[7]) == 0u;
}
__device__ __forceinline__ int2 load_edge(const void* ei, int e, bool is64) {
    int2 r;
    if (is64) {
        const long long* p = (const long long*)ei;
        r.x = (int)p[e];
        r.y = (int)p[Ee + e];
    } else {
        const int* p = (const int*)ei;
        r.x = p[e];
        r.y = p[Ee + e];
    }
    return r;
}

// ---------------- adjacency build ----------------
__global__ void k_scatter(const void* __restrict__ ei) {
    int e = blockIdx.x * blockDim.x + threadIdx.x;
    if (e < Nn) g_cnt[e] = 0;
    if (e >= Ee) return;
    bool is64 = edge_is64(ei);
    int2 sd = load_edge(ei, e, is64);
    if ((unsigned)sd.x >= Nn || (unsigned)sd.y >= Nn) return;
    atomicMax(&g_winner[sd.y * Nn + sd.x], e + 1);
}

__global__ void k_append(const void* __restrict__ ei, const float* __restrict__ ew) {
    int e = blockIdx.x * blockDim.x + threadIdx.x;
    if (e < Nn && g_winner[e * Nn + e] == 0) {       // self edge (diag not overridden)
        int s = atomicAdd(&g_cnt[e], 1);
        if (s < MAXNB) { g_cols[e * MAXNB + s] = e; g_wts[e * MAXNB + s] = 0.0f; }
    }
    if (e >= Ee) return;
    bool is64 = edge_is64(ei);
    int2 sd = load_edge(ei, e, is64);
    if ((unsigned)sd.x >= Nn || (unsigned)sd.y >= Nn) return;
    if (g_winner[sd.y * Nn + sd.x] == e + 1) {       // surviving write for (dst,src)
        int s = atomicAdd(&g_cnt[sd.y], 1);
        if (s < MAXNB) { g_cols[sd.y * MAXNB + s] = sd.x; g_wts[sd.y * MAXNB + s] = ew[e]; }
    }
}

__global__ void k_cleanup(const void* __restrict__ ei) {
    int e = blockIdx.x * blockDim.x + threadIdx.x;
    if (e >= Ee) return;
    bool is64 = edge_is64(ei);
    int2 sd = load_edge(ei, e, is64);
    if ((unsigned)sd.x >= Nn || (unsigned)sd.y >= Nn) return;
    g_winner[sd.y * Nn + sd.x] = 0;                  // restore zero-state for next replay
}

// ---------------- tf32 mma GEMM: C[M,N] = A[M,K] * B[N,K]^T + bias[N] ----------------
// 128x128 CTA tile, 4 warps of 64x64, K-slab 16, 4-stage cp.async.cg, ldmatrix frags,
// NO in-loop cvt (operands pre-rounded to tf32).
#define BM 128
#define BN 128
#define SLAB 16
#define NSLAB (Dd / SLAB)   // 32
#define SPAD 20             // row stride floats: 80B (16B-aligned, ldmatrix conflict-free)
#define NSTAGE 4
#define GEMM_SMEM (NSTAGE * (BM + BN) * SPAD * 4)   // 81920 B

template<int MODE>
__global__ __launch_bounds__(128) void tc_gemm(const float* __restrict__ bias)
{
    constexpr int N = (MODE == 0) ? D3 : Dd;
    constexpr int K = Dd;
    const float* A  = (MODE == 0) ? (const float*)g_xr
                    : (MODE == 1) ? (const float*)g_attn : (const float*)g_h1r;
    const float* Bw = (MODE == 0) ? (const float*)g_wqkvr
                    : (MODE == 1) ? (const float*)g_wor : (const float*)g_w1r;
    float* C = (MODE == 0) ? (float*)g_qkv : (float*)g_tmp;

    extern __shared__ float smf[];
    uint32_t smb = smem_u32(smf);
    const uint32_t AST  = BM * SPAD * 4;     // bytes per A stage
    const uint32_t BST  = BN * SPAD * 4;
    const uint32_t BOFF = NSTAGE * AST;

    int tid  = threadIdx.x;
    int warp = tid >> 5;
    int lane = tid & 31;
    int g  = lane >> 2;
    int t4 = lane & 3;
    int wRow = (warp >> 1) * 64;
    int wCol = (warp & 1) * 64;

    int rowBase = blockIdx.y * BM;
    int colBase = blockIdx.x * BN;

    const float* Ag = A  + (size_t)(rowBase + tid) * K;   // one row per thread
    const float* Bg = Bw + (size_t)(colBase + tid) * K;
    uint32_t aDst = smb + tid * SPAD * 4;
    uint32_t bDst = smb + BOFF + tid * SPAD * 4;

    // ldmatrix lane-address bases (stage 0)
    uint32_t aFrag = smb + 4u * ((wRow + (lane & 15)) * SPAD + ((lane >> 4) & 1) * 4);
    uint32_t bFrag = smb + BOFF +
        4u * ((wCol + (lane & 7) + ((lane >> 4) & 1) * 8) * SPAD + ((lane >> 3) & 1) * 4);

    float acc[4][8][4];
    #pragma unroll
    for (int mt = 0; mt < 4; mt++)
        #pragma unroll
        for (int nt = 0; nt < 8; nt++)
            #pragma unroll
            for (int j = 0; j < 4; j++) acc[mt][nt][j] = 0.0f;

    // prologue: stage slabs 0..NSTAGE-2
    #pragma unroll
    for (int st = 0; st < NSTAGE - 1; st++) {
        #pragma unroll
        for (int c = 0; c < 4; c++) {
            cp16cg(aDst + st * AST + c * 16, Ag + st * SLAB + c * 4);
            cp16cg(bDst + st * BST + c * 16, Bg + st * SLAB + c * 4);
        }
        asm volatile("cp.async.commit_group;" ::: "memory");
    }

    for (int s = 0; s < NSLAB; s++) {
        asm volatile("cp.async.wait_group %0;" :: "n"(NSTAGE - 2) : "memory");
        __syncthreads();    // slab s ready; everyone done with slab s-1's buffer

        int ns = s + NSTAGE - 1;
        if (ns < NSLAB) {
            int stn = ns & (NSTAGE - 1);
            #pragma unroll
            for (int c = 0; c < 4; c++) {
                cp16cg(aDst + stn * AST + c * 16, Ag + ns * SLAB + c * 4);
                cp16cg(bDst + stn * BST + c * 16, Bg + ns * SLAB + c * 4);
            }
        }
        asm volatile("cp.async.commit_group;" ::: "memory");   // empty group at tail keeps accounting

        int st = s & (NSTAGE - 1);
        uint32_t ao = aFrag + st * AST;
        uint32_t bo = bFrag + st * BST;

        #pragma unroll
        for (int ks = 0; ks < SLAB; ks += 8) {
            uint32_t ua[4][4], ub[4][4];
            #pragma unroll
            for (int mt = 0; mt < 4; mt++)
                ldsm4(ua[mt], ao + 4u * (mt * 16 * SPAD + ks));
            #pragma unroll
            for (int p = 0; p < 4; p++)
                ldsm4(ub[p], bo + 4u * (p * 16 * SPAD + ks));
            #pragma unroll
            for (int mt = 0; mt < 4; mt++) {
                #pragma unroll
                for (int p = 0; p < 4; p++) {
                    mma8(acc[mt][2 * p],     ua[mt], &ub[p][0]);
                    mma8(acc[mt][2 * p + 1], ua[mt], &ub[p][2]);
                }
            }
        }
    }

    // epilogue: c0,c1 -> (row g, col 2*t4..+1); c2,c3 -> row g+8
    #pragma unroll
    for (int mt = 0; mt < 4; mt++) {
        #pragma unroll
        for (int nt = 0; nt < 8; nt++) {
            float* cf = acc[mt][nt];
            int r  = rowBase + wRow + mt * 16 + g;
            int cc = colBase + wCol + nt * 8 + t4 * 2;
            float bx = bias[cc], by = bias[cc + 1];
            *(float2*)(C + (size_t)r * N + cc)       = make_float2(cf[0] + bx, cf[1] + by);
            *(float2*)(C + (size_t)(r + 8) * N + cc) = make_float2(cf[2] + bx, cf[3] + by);
        }
    }
}

// ---------------- sparse attention: one block per query row, one warp per head ----------------
// output written tf32-pre-rounded (consumed only by tc_gemm<1>)
__global__ __launch_bounds__(256) void sparse_attn() {
    int i = blockIdx.x;
    int h = threadIdx.x >> 5;
    int lane = threadIdx.x & 31;
    int cnt = g_cnt[i];
    if (cnt > MAXNB) cnt = MAXNB;

    __shared__ float sc[HEADS][MAXNB];
    __shared__ int   cols_s[MAXNB];
    __shared__ float wts_s[MAXNB];

    for (int t = threadIdx.x; t < cnt; t += 256) {
        cols_s[t] = g_cols[i * MAXNB + t];
        wts_s[t]  = g_wts[i * MAXNB + t];
    }
    __syncthreads();

    float2 qv = *(const float2*)(g_qkv + (size_t)i * D3 + h * HD + lane * 2);

    for (int t0 = 0; t0 < cnt; t0 += 4) {
        float d[4] = {0.f, 0.f, 0.f, 0.f};
        #pragma unroll
        for (int u = 0; u < 4; u++) {
            int t = t0 + u;
            if (t < cnt) {
                int j = cols_s[t];
                float2 kv = *(const float2*)(g_qkv + (size_t)j * D3 + Dd + h * HD + lane * 2);
                d[u] = qv.x * kv.x + qv.y * kv.y;
            }
        }
        #pragma unroll
        for (int o = 16; o; o >>= 1) {
            d[0] += __shfl_xor_sync(0xffffffffu, d[0], o);
            d[1] += __shfl_xor_sync(0xffffffffu, d[1], o);
            d[2] += __shfl_xor_sync(0xffffffffu, d[2], o);
            d[3] += __shfl_xor_sync(0xffffffffu, d[3], o);
        }
        if (lane == 0) {
            #pragma unroll
            for (int u = 0; u < 4; u++)
                if (t0 + u < cnt) sc[h][t0 + u] = d[u] * 0.125f + wts_s[t0 + u];
        }
    }
    __syncwarp();

    float m = -1e30f;
    for (int t = lane; t < cnt; t += 32) m = fmaxf(m, sc[h][t]);
    #pragma unroll
    for (int o = 16; o; o >>= 1) m = fmaxf(m, __shfl_xor_sync(0xffffffffu, m, o));

    float s = 0.0f;
    for (int t = lane; t < cnt; t += 32) {
        float e = expf(sc[h][t] - m);
        sc[h][t] = e;
        s += e;
    }
    #pragma unroll
    for (int o = 16; o; o >>= 1) s += __shfl_xor_sync(0xffffffffu, s, o);
    float inv = 1.0f / s;
    __syncwarp();

    float2 acc = make_float2(0.0f, 0.0f);
    for (int t = 0; t < cnt; t++) {
        float p = sc[h][t] * inv;
        int j = cols_s[t];
        float2 vv = *(const float2*)(g_qkv + (size_t)j * D3 + 2 * Dd + h * HD + lane * 2);
        acc.x += p * vv.x;
        acc.y += p * vv.y;
    }
    float* op = g_attn + (size_t)i * Dd + h * HD + lane * 2;
    op[0] = roundtf(acc.x);    // pre-round for tc_gemm<1> (same rna as before)
    op[1] = roundtf(acc.y);
}

// ---------------- add + LayerNorm ----------------
// MODE 0: g_h1 = LN(x_arg + g_tmp) exact, plus g_h1r = tf32-rounded copy
// MODE 1: out_ext = LN(g_h1 + g_tmp)
template<int MODE>
__global__ __launch_bounds__(256) void add_ln(
    const float* __restrict__ a_in,
    const float* __restrict__ g, const float* __restrict__ be,
    float* __restrict__ out_ext)
{
    const float* a = (MODE == 0) ? a_in : (const float*)g_h1;
    const float* b = (const float*)g_tmp;
    float*       o = (MODE == 0) ? (float*)g_h1 : out_ext;

    int i = blockIdx.x;
    int t = threadIdx.x;
    int lane = t & 31, w = t >> 5;
    __shared__ float sh[8];

    float2 av = *(const float2*)(a + (size_t)i * Dd + t * 2);
    float2 bv = *(const float2*)(b + (size_t)i * Dd + t * 2);
    float yx = av.x + bv.x;
    float yy = av.y + bv.y;

    float s = yx + yy;
    #pragma unroll
    for (int oo = 16; oo; oo >>= 1) s += __shfl_xor_sync(0xffffffffu, s, oo);
    if (lane == 0) sh[w] = s;
    __syncthreads();
    if (t == 0) {
        float tot = 0;
        #pragma unroll
        for (int k = 0; k < 8; k++) tot += sh[k];
        sh[0] = tot;
    }
    __syncthreads();
    float mu = sh[0] * (1.0f / Dd);
    __syncthreads();

    float dx = yx - mu, dy = yy - mu;
    float qq = dx * dx + dy * dy;
    #pragma unroll
    for (int oo = 16; oo; oo >>= 1) qq += __shfl_xor_sync(0xffffffffu, qq, oo);
    if (lane == 0) sh[w] = qq;
    __syncthreads();
    if (t == 0) {
        float tot = 0;
        #pragma unroll
        for (int k = 0; k < 8; k++) tot += sh[k];
        sh[0] = tot;
    }
    __syncthreads();
    float var = sh[0] * (1.0f / Dd);
    float r = rsqrtf(var + 1e-5f);

    float2 gv  = *(const float2*)(g + t * 2);
    float2 bev = *(const float2*)(be + t * 2);
    float2 o2;
    o2.x = dx * r * gv.x + bev.x;
    o2.y = dy * r * gv.y + bev.y;
    *(float2*)(o + (size_t)i * Dd + t * 2) = o2;
    if (MODE == 0) {
        float2 o2r = make_float2(roundtf(o2.x), roundtf(o2.y));
        *(float2*)((float*)g_h1r + (size_t)i * Dd + t * 2) = o2r;
    }
}

// ---------------- launch ----------------
extern "C" void kernel_launch(void* const* d_in, const int* in_sizes, int n_in,
                              void* d_out, int out_size) {
    const float* x    = (const float*)d_in[0];
    const void*  ei   = d_in[1];
    const float* ew   = (const float*)d_in[2];
    const float* Wqkv = (const float*)d_in[3];
    const float* bqkv = (const float*)d_in[4];
    const float* Wo   = (const float*)d_in[5];
    const float* bo   = (const float*)d_in[6];
    const float* W1   = (const float*)d_in[7];
    const float* b1   = (const float*)d_in[8];
    const float* g1   = (const float*)d_in[9];
    const float* be1  = (const float*)d_in[10];
    const float* g2   = (const float*)d_in[11];
    const float* be2  = (const float*)d_in[12];
    float* out = (float*)d_out;

    cudaFuncSetAttribute(tc_gemm<0>, cudaFuncAttributeMaxDynamicSharedMemorySize, GEMM_SMEM);
    cudaFuncSetAttribute(tc_gemm<1>, cudaFuncAttributeMaxDynamicSharedMemorySize, GEMM_SMEM);
    cudaFuncSetAttribute(tc_gemm<2>, cudaFuncAttributeMaxDynamicSharedMemorySize, GEMM_SMEM);

    // adjacency with exact last-write-wins dedup (winner grid self-restores to zero)
    k_scatter<<<Ee / 256, 256>>>(ei);
    k_append<<<Ee / 256, 256>>>(ei, ew);
    k_cleanup<<<Ee / 256, 256>>>(ei);

    // pre-round GEMM operands to tf32 (rna; same rounding points as before)
    k_round<0><<<(Nn * Dd / 4 + 255) / 256, 256>>>(x);
    k_round<1><<<(D3 * Dd / 4 + 255) / 256, 256>>>(Wqkv);
    k_round<2><<<(Dd * Dd / 4 + 255) / 256, 256>>>(Wo);
    k_round<3><<<(Dd * Dd / 4 + 255) / 256, 256>>>(W1);

    // qkv = x @ Wqkv^T + bqkv            -> g_qkv
    tc_gemm<0><<<dim3(D3 / BN, Nn / BM), 128, GEMM_SMEM>>>(bqkv);

    // sparse multi-head attention        -> g_attn (tf32-rounded)
    sparse_attn<<<Nn, 256>>>();

    // attn_out = g_attn @ Wo^T + bo      -> g_tmp
    tc_gemm<1><<<dim3(Dd / BN, Nn / BM), 128, GEMM_SMEM>>>(bo);

    // h1 = LN(x + g_tmp)                 -> g_h1 (exact) + g_h1r (rounded)
    add_ln<0><<<Nn, 256>>>(x, g1, be1, out);

    // ffn = g_h1 @ W1^T + b1             -> g_tmp
    tc_gemm<2><<<dim3(Dd / BN, Nn / BM), 128, GEMM_SMEM>>>(b1);

    // out = LN(g_h1 + g_tmp)             -> out
    add_ln<1><<<Nn, 256>>>(nullptr, g2, be2, out);
}

// round 11
// speedup vs baseline: 1.0879x; 1.0879x over previous
#include <cuda_runtime.h>
#include <math.h>
#include <stdint.h>

#define Nn 4096
#define Dd 512
#define D3 1536
#define Ee 131072
#define MAXNB 128
#define HEADS 8
#define HD 64

// ---------------- scratch (device globals; referenced ONLY from device code) ----------------
__device__ int   g_winner[Nn * Nn];     // 0 = empty; else edge_id+1 (zero-init, self-restoring)
__device__ __align__(128) int   g_cnt[Nn];
__device__ __align__(128) int   g_cols[Nn * MAXNB];
__device__ __align__(128) float g_wts[Nn * MAXNB];
__device__ __align__(128) float g_qkv[Nn * D3];
__device__ __align__(128) float g_attn[Nn * Dd];    // written pre-rounded to tf32
__device__ __align__(128) float g_tmp[Nn * Dd];
__device__ __align__(128) float g_h1[Nn * Dd];      // exact (for residual)
__device__ __align__(128) float g_h1r[Nn * Dd];     // tf32-rounded (GEMM operand)
__device__ __align__(128) float g_xr[Nn * Dd];      // tf32-rounded x
__device__ __align__(128) float g_wqkvr[D3 * Dd];   // tf32-rounded weights
__device__ __align__(128) float g_wor[Dd * Dd];
__device__ __align__(128) float g_w1r[Dd * Dd];

// ---------------- helpers ----------------
__device__ __forceinline__ uint32_t smem_u32(const void* p) {
    uint32_t a;
    asm("{ .reg .u64 t; cvta.to.shared.u64 t, %1; cvt.u32.u64 %0, t; }" : "=r"(a) : "l"(p));
    return a;
}
__device__ __forceinline__ uint32_t f2tf(uint32_t fb) {
    uint32_t u;
    asm("cvt.rna.tf32.f32 %0, %1;" : "=r"(u) : "f"(__uint_as_float(fb)));
    return u;
}
__device__ __forceinline__ float roundtf(float f) {
    return __uint_as_float(f2tf(__float_as_uint(f)));
}
__device__ __forceinline__ void cp16cg(uint32_t dst, const void* src) {
    asm volatile("cp.async.cg.shared.global [%0], [%1], 16;" :: "r"(dst), "l"(src));
}
__device__ __forceinline__ void ldsm4(uint32_t* r, uint32_t addr) {
    asm volatile("ldmatrix.sync.aligned.m8n8.x4.shared.b16 {%0,%1,%2,%3}, [%4];"
        : "=r"(r[0]), "=r"(r[1]), "=r"(r[2]), "=r"(r[3]) : "r"(addr));
}
__device__ __forceinline__ void mma8(float* c, const uint32_t* a, const uint32_t* b) {
    asm volatile(
        "mma.sync.aligned.m16n8k8.row.col.f32.tf32.tf32.f32 "
        "{%0,%1,%2,%3},{%4,%5,%6,%7},{%8,%9},{%0,%1,%2,%3};"
        : "+f"(c[0]), "+f"(c[1]), "+f"(c[2]), "+f"(c[3])
        : "r"(a[0]), "r"(a[1]), "r"(a[2]), "r"(a[3]), "r"(b[0]), "r"(b[1]));
}

// ---------------- fused tf32 pre-round (x | Wqkv | Wo | W1 in one grid) ----------------
#define R_X   (Nn * Dd / 4)
#define R_WQ  (D3 * Dd / 4)
#define R_WO  (Dd * Dd / 4)
#define R_TOT (R_X + R_WQ + 2 * R_WO)

__global__ void k_round_all(const float* __restrict__ x, const float* __restrict__ wq,
                            const float* __restrict__ wo, const float* __restrict__ w1)
{
    int i = blockIdx.x * 256 + threadIdx.x;
    if (i >= R_TOT) return;
    const float4* src;
    float4* dst;
    if (i < R_X)                       { src = (const float4*)x  + i;                 dst = (float4*)g_xr    + i; }
    else if (i < R_X + R_WQ)           { src = (const float4*)wq + (i - R_X);         dst = (float4*)g_wqkvr + (i - R_X); }
    else if (i < R_X + R_WQ + R_WO)    { src = (const float4*)wo + (i - R_X - R_WQ);  dst = (float4*)g_wor   + (i - R_X - R_WQ); }
    else                               { src = (const float4*)w1 + (i - R_X - R_WQ - R_WO); dst = (float4*)g_w1r + (i - R_X - R_WQ - R_WO); }
    float4 v = *src;
    v.x = roundtf(v.x); v.y = roundtf(v.y); v.z = roundtf(v.z); v.w = roundtf(v.w);
    *dst = v;
}

// ---------------- edge access (dtype auto-detect per-thread) ----------------
__device__ __forceinline__ bool edge_is64(const void* ei) {
    const uint32_t* w = (const uint32_t*)ei;
    return (w[1] | w[3] | w[5] | w[7]) == 0u;
}
__device__ __forceinline__ int2 load_edge(const void* ei, int e, bool is64) {
    int2 r;
    if (is64) {
        const long long* p = (const long long*)ei;
        r.x = (int)p[e];
        r.y = (int)p[Ee + e];
    } else {
        const int* p = (const int*)ei;
        r.x = p[e];
        r.y = p[Ee + e];
    }
    return r;
}

// ---------------- adjacency build ----------------
__global__ void k_scatter(const void* __restrict__ ei) {
    int e = blockIdx.x * blockDim.x + threadIdx.x;
    if (e < Nn) g_cnt[e] = 0;
    if (e >= Ee) return;
    bool is64 = edge_is64(ei);
    int2 sd = load_edge(ei, e, is64);
    if ((unsigned)sd.x >= Nn || (unsigned)sd.y >= Nn) return;
    atomicMax(&g_winner[sd.y * Nn + sd.x], e + 1);
}

// winner cells (non-diagonal) are zeroed here by the winning edge after use;
// losers compare against their own e+1, so reading 0 or e_win+1 both miss.
// Diagonal cells (read by the self-check) are cleaned afterwards by k_cleanup_diag.
__global__ void k_append(const void* __restrict__ ei, const float* __restrict__ ew) {
    int e = blockIdx.x * blockDim.x + threadIdx.x;
    if (e < Nn && g_winner[e * Nn + e] == 0) {       // self edge (diag not overridden)
        int s = atomicAdd(&g_cnt[e], 1);
        if (s < MAXNB) { g_cols[e * MAXNB + s] = e; g_wts[e * MAXNB + s] = 0.0f; }
    }
    if (e >= Ee) return;
    bool is64 = edge_is64(ei);
    int2 sd = load_edge(ei, e, is64);
    if ((unsigned)sd.x >= Nn || (unsigned)sd.y >= Nn) return;
    if (g_winner[sd.y * Nn + sd.x] == e + 1) {       // surviving write for (dst,src)
        int s = atomicAdd(&g_cnt[sd.y], 1);
        if (s < MAXNB) { g_cols[sd.y * MAXNB + s] = sd.x; g_wts[sd.y * MAXNB + s] = ew[e]; }
        if (sd.x != sd.y) g_winner[sd.y * Nn + sd.x] = 0;   // restore for next replay
    }
}

__global__ void k_cleanup_diag() {
    int i = blockIdx.x * blockDim.x + threadIdx.x;
    if (i < Nn) g_winner[i * Nn + i] = 0;
}

// ---------------- tf32 mma GEMM: C[M,N] = A[M,K] * B[N,K]^T + bias[N] ----------------
// 128x128 CTA tile, 8 warps of 64x32 (2 CTAs/SM -> 16 warps/SM), K-slab 16,
// 4-stage cp.async.cg, ldmatrix frags, operands pre-rounded to tf32.
#define BM 128
#define BN 128
#define SLAB 16
#define NSLAB (Dd / SLAB)   // 32
#define SPAD 20             // row stride floats: 80B (16B-aligned, ldmatrix conflict-free)
#define NSTAGE 4
#define GEMM_SMEM (NSTAGE * (BM + BN) * SPAD * 4)   // 81920 B

template<int MODE>
__global__ __launch_bounds__(256, 2) void tc_gemm(const float* __restrict__ bias)
{
    constexpr int N = (MODE == 0) ? D3 : Dd;
    constexpr int K = Dd;
    const float* A  = (MODE == 0) ? (const float*)g_xr
                    : (MODE == 1) ? (const float*)g_attn : (const float*)g_h1r;
    const float* Bw = (MODE == 0) ? (const float*)g_wqkvr
                    : (MODE == 1) ? (const float*)g_wor : (const float*)g_w1r;
    float* C = (MODE == 0) ? (float*)g_qkv : (float*)g_tmp;

    extern __shared__ float smf[];
    uint32_t smb = smem_u32(smf);
    const uint32_t AST  = BM * SPAD * 4;     // bytes per A stage
    const uint32_t BST  = BN * SPAD * 4;
    const uint32_t BOFF = NSTAGE * AST;

    int tid  = threadIdx.x;
    int warp = tid >> 5;
    int lane = tid & 31;
    int g  = lane >> 2;
    int t4 = lane & 3;
    int wRow = (warp >> 2) * 64;     // 0 or 64
    int wCol = (warp & 3) * 32;      // 0,32,64,96

    int rowBase = blockIdx.y * BM;
    int colBase = blockIdx.x * BN;

    // staging: threads 0-127 load A rows, 128-255 load B rows (4 cp16 per slab each)
    int ldr = tid & 127;
    bool isB = tid >= 128;
    const float* Gp = isB ? (Bw + (size_t)(colBase + ldr) * K)
                          : (A  + (size_t)(rowBase + ldr) * K);
    uint32_t sDst = smb + (isB ? BOFF : 0u) + ldr * SPAD * 4;
    const uint32_t SST = isB ? BST : AST;

    // ldmatrix lane-address bases (stage 0)
    uint32_t aFrag = smb + 4u * ((wRow + (lane & 15)) * SPAD + ((lane >> 4) & 1) * 4);
    uint32_t bFrag = smb + BOFF +
        4u * ((wCol + (lane & 7) + ((lane >> 4) & 1) * 8) * SPAD + ((lane >> 3) & 1) * 4);

    float acc[4][4][4];
    #pragma unroll
    for (int mt = 0; mt < 4; mt++)
        #pragma unroll
        for (int nt = 0; nt < 4; nt++)
            #pragma unroll
            for (int j = 0; j < 4; j++) acc[mt][nt][j] = 0.0f;

    // prologue: stage slabs 0..NSTAGE-2
    #pragma unroll
    for (int st = 0; st < NSTAGE - 1; st++) {
        #pragma unroll
        for (int c = 0; c < 4; c++)
            cp16cg(sDst + st * SST + c * 16, Gp + st * SLAB + c * 4);
        asm volatile("cp.async.commit_group;" ::: "memory");
    }

    for (int s = 0; s < NSLAB; s++) {
        asm volatile("cp.async.wait_group %0;" :: "n"(NSTAGE - 2) : "memory");
        __syncthreads();    // slab s ready; everyone done with the buffer being refilled

        int ns = s + NSTAGE - 1;
        if (ns < NSLAB) {
            int stn = ns & (NSTAGE - 1);
            #pragma unroll
            for (int c = 0; c < 4; c++)
                cp16cg(sDst + stn * SST + c * 16, Gp + ns * SLAB + c * 4);
        }
        asm volatile("cp.async.commit_group;" ::: "memory");   // empty group at tail keeps accounting

        int st = s & (NSTAGE - 1);
        uint32_t ao = aFrag + st * AST;
        uint32_t bo = bFrag + st * BST;

        #pragma unroll
        for (int ks = 0; ks < SLAB; ks += 8) {
            uint32_t ua[4][4], ub[2][4];
            #pragma unroll
            for (int mt = 0; mt < 4; mt++)
                ldsm4(ua[mt], ao + 4u * (mt * 16 * SPAD + ks));
            #pragma unroll
            for (int p = 0; p < 2; p++)
                ldsm4(ub[p], bo + 4u * (p * 16 * SPAD + ks));
            #pragma unroll
            for (int mt = 0; mt < 4; mt++) {
                #pragma unroll
                for (int p = 0; p < 2; p++) {
                    mma8(acc[mt][2 * p],     ua[mt], &ub[p][0]);
                    mma8(acc[mt][2 * p + 1], ua[mt], &ub[p][2]);
                }
            }
        }
    }

    // epilogue: c0,c1 -> (row g, col 2*t4..+1); c2,c3 -> row g+8
    #pragma unroll
    for (int mt = 0; mt < 4; mt++) {
        #pragma unroll
        for (int nt = 0; nt < 4; nt++) {
            float* cf = acc[mt][nt];
            int r  = rowBase + wRow + mt * 16 + g;
            int cc = colBase + wCol + nt * 8 + t4 * 2;
            float bx = bias[cc], by = bias[cc + 1];
            *(float2*)(C + (size_t)r * N + cc)       = make_float2(cf[0] + bx, cf[1] + by);
            *(float2*)(C + (size_t)(r + 8) * N + cc) = make_float2(cf[2] + bx, cf[3] + by);
        }
    }
}

// ---------------- sparse attention: one block per query row, one warp per head ----------------
// output written tf32-pre-rounded (consumed only by tc_gemm<1>)
__global__ __launch_bounds__(256) void sparse_attn() {
    int i = blockIdx.x;
    int h = threadIdx.x >> 5;
    int lane = threadIdx.x & 31;
    int cnt = g_cnt[i];
    if (cnt > MAXNB) cnt = MAXNB;

    __shared__ float sc[HEADS][MAXNB];
    __shared__ int   cols_s[MAXNB];
    __shared__ float wts_s[MAXNB];

    for (int t = threadIdx.x; t < cnt; t += 256) {
        cols_s[t] = g_cols[i * MAXNB + t];
        wts_s[t]  = g_wts[i * MAXNB + t];
    }
    __syncthreads();

    float2 qv = *(const float2*)(g_qkv + (size_t)i * D3 + h * HD + lane * 2);

    for (int t0 = 0; t0 < cnt; t0 += 4) {
        float d[4] = {0.f, 0.f, 0.f, 0.f};
        #pragma unroll
        for (int u = 0; u < 4; u++) {
            int t = t0 + u;
            if (t < cnt) {
                int j = cols_s[t];
                float2 kv = *(const float2*)(g_qkv + (size_t)j * D3 + Dd + h * HD + lane * 2);
                d[u] = qv.x * kv.x + qv.y * kv.y;
            }
        }
        #pragma unroll
        for (int o = 16; o; o >>= 1) {
            d[0] += __shfl_xor_sync(0xffffffffu, d[0], o);
            d[1] += __shfl_xor_sync(0xffffffffu, d[1], o);
            d[2] += __shfl_xor_sync(0xffffffffu, d[2], o);
            d[3] += __shfl_xor_sync(0xffffffffu, d[3], o);
        }
        if (lane == 0) {
            #pragma unroll
            for (int u = 0; u < 4; u++)
                if (t0 + u < cnt) sc[h][t0 + u] = d[u] * 0.125f + wts_s[t0 + u];
        }
    }
    __syncwarp();

    float m = -1e30f;
    for (int t = lane; t < cnt; t += 32) m = fmaxf(m, sc[h][t]);
    #pragma unroll
    for (int o = 16; o; o >>= 1) m = fmaxf(m, __shfl_xor_sync(0xffffffffu, m, o));

    float s = 0.0f;
    for (int t = lane; t < cnt; t += 32) {
        float e = expf(sc[h][t] - m);
        sc[h][t] = e;
        s += e;
    }
    #pragma unroll
    for (int o = 16; o; o >>= 1) s += __shfl_xor_sync(0xffffffffu, s, o);
    float inv = 1.0f / s;
    __syncwarp();

    float2 acc = make_float2(0.0f, 0.0f);
    for (int t = 0; t < cnt; t++) {
        float p = sc[h][t] * inv;
        int j = cols_s[t];
        float2 vv = *(const float2*)(g_qkv + (size_t)j * D3 + 2 * Dd + h * HD + lane * 2);
        acc.x += p * vv.x;
        acc.y += p * vv.y;
    }
    float* op = g_attn + (size_t)i * Dd + h * HD + lane * 2;
    op[0] = roundtf(acc.x);    // pre-round for tc_gemm<1>
    op[1] = roundtf(acc.y);
}

// ---------------- add + LayerNorm ----------------
// MODE 0: g_h1 = LN(x_arg + g_tmp) exact, plus g_h1r = tf32-rounded copy
// MODE 1: out_ext = LN(g_h1 + g_tmp)
template<int MODE>
__global__ __launch_bounds__(256) void add_ln(
    const float* __restrict__ a_in,
    const float* __restrict__ g, const float* __restrict__ be,
    float* __restrict__ out_ext)
{
    const float* a = (MODE == 0) ? a_in : (const float*)g_h1;
    const float* b = (const float*)g_tmp;
    float*       o = (MODE == 0) ? (float*)g_h1 : out_ext;

    int i = blockIdx.x;
    int t = threadIdx.x;
    int lane = t & 31, w = t >> 5;
    __shared__ float sh[8];

    float2 av = *(const float2*)(a + (size_t)i * Dd + t * 2);
    float2 bv = *(const float2*)(b + (size_t)i * Dd + t * 2);
    float yx = av.x + bv.x;
    float yy = av.y + bv.y;

    float s = yx + yy;
    #pragma unroll
    for (int oo = 16; oo; oo >>= 1) s += __shfl_xor_sync(0xffffffffu, s, oo);
    if (lane == 0) sh[w] = s;
    __syncthreads();
    if (t == 0) {
        float tot = 0;
        #pragma unroll
        for (int k = 0; k < 8; k++) tot += sh[k];
        sh[0] = tot;
    }
    __syncthreads();
    float mu = sh[0] * (1.0f / Dd);
    __syncthreads();

    float dx = yx - mu, dy = yy - mu;
    float qq = dx * dx + dy * dy;
    #pragma unroll
    for (int oo = 16; oo; oo >>= 1) qq += __shfl_xor_sync(0xffffffffu, qq, oo);
    if (lane == 0) sh[w] = qq;
    __syncthreads();
    if (t == 0) {
        float tot = 0;
        #pragma unroll
        for (int k = 0; k < 8; k++) tot += sh[k];
        sh[0] = tot;
    }
    __syncthreads();
    float var = sh[0] * (1.0f / Dd);
    float r = rsqrtf(var + 1e-5f);

    float2 gv  = *(const float2*)(g + t * 2);
    float2 bev = *(const float2*)(be + t * 2);
    float2 o2;
    o2.x = dx * r * gv.x + bev.x;
    o2.y = dy * r * gv.y + bev.y;
    *(float2*)(o + (size_t)i * Dd + t * 2) = o2;
    if (MODE == 0) {
        float2 o2r = make_float2(roundtf(o2.x), roundtf(o2.y));
        *(float2*)((float*)g_h1r + (size_t)i * Dd + t * 2) = o2r;
    }
}

// ---------------- launch ----------------
extern "C" void kernel_launch(void* const* d_in, const int* in_sizes, int n_in,
                              void* d_out, int out_size) {
    const float* x    = (const float*)d_in[0];
    const void*  ei   = d_in[1];
    const float* ew   = (const float*)d_in[2];
    const float* Wqkv = (const float*)d_in[3];
    const float* bqkv = (const float*)d_in[4];
    const float* Wo   = (const float*)d_in[5];
    const float* bo   = (const float*)d_in[6];
    const float* W1   = (const float*)d_in[7];
    const float* b1   = (const float*)d_in[8];
    const float* g1   = (const float*)d_in[9];
    const float* be1  = (const float*)d_in[10];
    const float* g2   = (const float*)d_in[11];
    const float* be2  = (const float*)d_in[12];
    float* out = (float*)d_out;

    cudaFuncSetAttribute(tc_gemm<0>, cudaFuncAttributeMaxDynamicSharedMemorySize, GEMM_SMEM);
    cudaFuncSetAttribute(tc_gemm<1>, cudaFuncAttributeMaxDynamicSharedMemorySize, GEMM_SMEM);
    cudaFuncSetAttribute(tc_gemm<2>, cudaFuncAttributeMaxDynamicSharedMemorySize, GEMM_SMEM);

    // adjacency with exact last-write-wins dedup (winner grid self-restores to zero)
    k_scatter<<<Ee / 256, 256>>>(ei);
    k_append<<<Ee / 256, 256>>>(ei, ew);
    k_cleanup_diag<<<Nn / 256, 256>>>();

    // pre-round all GEMM operands to tf32 in one pass
    k_round_all<<<(R_TOT + 255) / 256, 256>>>(x, Wqkv, Wo, W1);

    // qkv = x @ Wqkv^T + bqkv            -> g_qkv
    tc_gemm<0><<<dim3(D3 / BN, Nn / BM), 256, GEMM_SMEM>>>(bqkv);

    // sparse multi-head attention        -> g_attn (tf32-rounded)
    sparse_attn<<<Nn, 256>>>();

    // attn_out = g_attn @ Wo^T + bo      -> g_tmp
    tc_gemm<1><<<dim3(Dd / BN, Nn / BM), 256, GEMM_SMEM>>>(bo);

    // h1 = LN(x + g_tmp)                 -> g_h1 (exact) + g_h1r (rounded)
    add_ln<0><<<Nn, 256>>>(x, g1, be1, out);

    // ffn = g_h1 @ W1^T + b1             -> g_tmp
    tc_gemm<2><<<dim3(Dd / BN, Nn / BM), 256, GEMM_SMEM>>>(b1);

    // out = LN(g_h1 + g_tmp)             -> out
    add_ln<1><<<Nn, 256>>>(nullptr, g2, be2, out);
}

// round 12
// speedup vs baseline: 1.2541x; 1.1528x over previous
#include <cuda_runtime.h>
#include <math.h>
#include <stdint.h>

#define Nn 4096
#define Dd 512
#define D3 1536
#define Ee 131072
#define MAXNB 128
#define HEADS 8
#define HD 64

// ---------------- scratch (device globals; referenced ONLY from device code) ----------------
__device__ int   g_winner[Nn * Nn];     // 0 = empty; else edge_id+1 (zero-init, self-restoring)
__device__ __align__(128) int   g_cnt[Nn];
__device__ __align__(128) int   g_cols[Nn * MAXNB];
__device__ __align__(128) float g_wts[Nn * MAXNB];
__device__ __align__(128) float g_qkv[Nn * D3];
__device__ __align__(128) float g_attn[Nn * Dd];    // written pre-rounded to tf32
__device__ __align__(128) float g_tmp[Nn * Dd];
__device__ __align__(128) float g_h1[Nn * Dd];      // exact (for residual)
__device__ __align__(128) float g_h1r[Nn * Dd];     // tf32-rounded (GEMM operand)
__device__ __align__(128) float g_xr[Nn * Dd];      // tf32-rounded x
__device__ __align__(128) float g_wqkvr[D3 * Dd];   // tf32-rounded weights
__device__ __align__(128) float g_wor[Dd * Dd];
__device__ __align__(128) float g_w1r[Dd * Dd];

// ---------------- helpers ----------------
__device__ __forceinline__ uint32_t smem_u32(const void* p) {
    uint32_t a;
    asm("{ .reg .u64 t; cvta.to.shared.u64 t, %1; cvt.u32.u64 %0, t; }" : "=r"(a) : "l"(p));
    return a;
}
__device__ __forceinline__ uint32_t f2tf(uint32_t fb) {
    uint32_t u;
    asm("cvt.rna.tf32.f32 %0, %1;" : "=r"(u) : "f"(__uint_as_float(fb)));
    return u;
}
__device__ __forceinline__ float roundtf(float f) {
    return __uint_as_float(f2tf(__float_as_uint(f)));
}
__device__ __forceinline__ void cp16cg(uint32_t dst, const void* src) {
    asm volatile("cp.async.cg.shared.global [%0], [%1], 16;" :: "r"(dst), "l"(src));
}
__device__ __forceinline__ void ldsm4(uint32_t* r, uint32_t addr) {
    asm volatile("ldmatrix.sync.aligned.m8n8.x4.shared.b16 {%0,%1,%2,%3}, [%4];"
        : "=r"(r[0]), "=r"(r[1]), "=r"(r[2]), "=r"(r[3]) : "r"(addr));
}
__device__ __forceinline__ void mma8(float* c, const uint32_t* a, const uint32_t* b) {
    asm volatile(
        "mma.sync.aligned.m16n8k8.row.col.f32.tf32.tf32.f32 "
        "{%0,%1,%2,%3},{%4,%5,%6,%7},{%8,%9},{%0,%1,%2,%3};"
        : "+f"(c[0]), "+f"(c[1]), "+f"(c[2]), "+f"(c[3])
        : "r"(a[0]), "r"(a[1]), "r"(a[2]), "r"(a[3]), "r"(b[0]), "r"(b[1]));
}

// ---------------- fused tf32 pre-round (x | Wqkv | Wo | W1 in one grid) ----------------
#define R_X   (Nn * Dd / 4)
#define R_WQ  (D3 * Dd / 4)
#define R_WO  (Dd * Dd / 4)
#define R_TOT (R_X + R_WQ + 2 * R_WO)

__global__ void k_round_all(const float* __restrict__ x, const float* __restrict__ wq,
                            const float* __restrict__ wo, const float* __restrict__ w1)
{
    int i = blockIdx.x * 256 + threadIdx.x;
    if (i >= R_TOT) return;
    const float4* src;
    float4* dst;
    if (i < R_X)                       { src = (const float4*)x  + i;                 dst = (float4*)g_xr    + i; }
    else if (i < R_X + R_WQ)           { src = (const float4*)wq + (i - R_X);         dst = (float4*)g_wqkvr + (i - R_X); }
    else if (i < R_X + R_WQ + R_WO)    { src = (const float4*)wo + (i - R_X - R_WQ);  dst = (float4*)g_wor   + (i - R_X - R_WQ); }
    else                               { src = (const float4*)w1 + (i - R_X - R_WQ - R_WO); dst = (float4*)g_w1r + (i - R_X - R_WQ - R_WO); }
    float4 v = *src;
    v.x = roundtf(v.x); v.y = roundtf(v.y); v.z = roundtf(v.z); v.w = roundtf(v.w);
    *dst = v;
}

// ---------------- edge access (dtype auto-detect per-thread) ----------------
__device__ __forceinline__ bool edge_is64(const void* ei) {
    const uint32_t* w = (const uint32_t*)ei;
    return (w[1] | w[3] | w[5] | w[7]) == 0u;
}
__device__ __forceinline__ int2 load_edge(const void* ei, int e, bool is64) {
    int2 r;
    if (is64) {
        const long long* p = (const long long*)ei;
        r.x = (int)p[e];
        r.y = (int)p[Ee + e];
    } else {
        const int* p = (const int*)ei;
        r.x = p[e];
        r.y = p[Ee + e];
    }
    return r;
}

// ---------------- adjacency build ----------------
__global__ void k_scatter(const void* __restrict__ ei) {
    int e = blockIdx.x * blockDim.x + threadIdx.x;
    if (e < Nn) g_cnt[e] = 0;
    if (e >= Ee) return;
    bool is64 = edge_is64(ei);
    int2 sd = load_edge(ei, e, is64);
    if ((unsigned)sd.x >= Nn || (unsigned)sd.y >= Nn) return;
    atomicMax(&g_winner[sd.y * Nn + sd.x], e + 1);
}

// winner cells (non-diagonal) are zeroed by the winning edge after use;
// losers compare against their own e+1, so reading 0 or e_win+1 both miss.
// Diagonal cells (read by the self-check) are cleaned afterwards by k_cleanup_diag.
__global__ void k_append(const void* __restrict__ ei, const float* __restrict__ ew) {
    int e = blockIdx.x * blockDim.x + threadIdx.x;
    if (e < Nn && g_winner[e * Nn + e] == 0) {       // self edge (diag not overridden)
        int s = atomicAdd(&g_cnt[e], 1);
        if (s < MAXNB) { g_cols[e * MAXNB + s] = e; g_wts[e * MAXNB + s] = 0.0f; }
    }
    if (e >= Ee) return;
    bool is64 = edge_is64(ei);
    int2 sd = load_edge(ei, e, is64);
    if ((unsigned)sd.x >= Nn || (unsigned)sd.y >= Nn) return;
    if (g_winner[sd.y * Nn + sd.x] == e + 1) {       // surviving write for (dst,src)
        int s = atomicAdd(&g_cnt[sd.y], 1);
        if (s < MAXNB) { g_cols[sd.y * MAXNB + s] = sd.x; g_wts[sd.y * MAXNB + s] = ew[e]; }
        if (sd.x != sd.y) g_winner[sd.y * Nn + sd.x] = 0;   // restore for next replay
    }
}

__global__ void k_cleanup_diag() {
    int i = blockIdx.x * blockDim.x + threadIdx.x;
    if (i < Nn) g_winner[i * Nn + i] = 0;
}

// ---------------- tf32 mma GEMM: C[M,N] = A[M,K] * B[N,K]^T + bias[N] ----------------
// BMv x 128 CTA tile (BMv = 128 or 64), 8 warps, K-slab 32, 3-stage cp.async.cg ring,
// ldmatrix fragments, operands pre-rounded to tf32.
#define BN 128
#define SLAB 32
#define NSLAB (Dd / SLAB)   // 16
#define SPAD 36             // row stride floats: 144B (16B-aligned, ldmatrix conflict-free)
#define NSTAGE 3

template<int MODE, int BMv>
__global__ __launch_bounds__(256, 2) void tc_gemm(const float* __restrict__ bias)
{
    constexpr int N = (MODE == 0) ? D3 : Dd;
    constexpr int K = Dd;
    constexpr int MT = BMv / 32;                    // m-tiles per warp (4 or 2)
    const float* A  = (MODE == 0) ? (const float*)g_xr
                    : (MODE == 1) ? (const float*)g_attn : (const float*)g_h1r;
    const float* Bw = (MODE == 0) ? (const float*)g_wqkvr
                    : (MODE == 1) ? (const float*)g_wor : (const float*)g_w1r;
    float* C = (MODE == 0) ? (float*)g_qkv : (float*)g_tmp;

    extern __shared__ float smf[];
    uint32_t smb = smem_u32(smf);
    constexpr uint32_t AST  = BMv * SPAD * 4;       // bytes per A stage
    constexpr uint32_t BST  = BN * SPAD * 4;
    constexpr uint32_t BOFF = NSTAGE * AST;

    int tid  = threadIdx.x;
    int warp = tid >> 5;
    int lane = tid & 31;
    int g  = lane >> 2;
    int t4 = lane & 3;
    int wRow = (warp >> 2) * (BMv / 2);             // 0 or BMv/2
    int wCol = (warp & 3) * 32;                     // 0,32,64,96

    int rowBase = blockIdx.y * BMv;
    int colBase = blockIdx.x * BN;

    // generic staging: quads over A then B
    constexpr int QPR = SLAB / 4;                   // quads per row (8)
    constexpr int AQ  = BMv * QPR;
    constexpr int TQ  = (BMv + BN) * QPR;

    // ldmatrix lane-address bases (stage 0)
    uint32_t aFrag = smb + 4u * ((wRow + (lane & 15)) * SPAD + ((lane >> 4) & 1) * 4);
    uint32_t bFrag = smb + BOFF +
        4u * ((wCol + (lane & 7) + ((lane >> 4) & 1) * 8) * SPAD + ((lane >> 3) & 1) * 4);

    float acc[MT][4][4];
    #pragma unroll
    for (int mt = 0; mt < MT; mt++)
        #pragma unroll
        for (int nt = 0; nt < 4; nt++)
            #pragma unroll
            for (int j = 0; j < 4; j++) acc[mt][nt][j] = 0.0f;

    // prologue: stage slabs 0..NSTAGE-2
    #pragma unroll
    for (int st = 0; st < NSTAGE - 1; st++) {
        for (int qd = tid; qd < TQ; qd += 256) {
            bool isB = qd >= AQ;
            int q2  = isB ? qd - AQ : qd;
            int row = q2 / QPR, quad = q2 % QPR;
            const float* src = (isB ? Bw + (size_t)(colBase + row) * K
                                    : A  + (size_t)(rowBase + row) * K) + st * SLAB + quad * 4;
            uint32_t dst = smb + (isB ? BOFF + st * BST : st * AST) + 4u * (row * SPAD + quad * 4);
            cp16cg(dst, src);
        }
        asm volatile("cp.async.commit_group;" ::: "memory");
    }

    for (int s = 0; s < NSLAB; s++) {
        asm volatile("cp.async.wait_group %0;" :: "n"(NSTAGE - 2) : "memory");
        __syncthreads();    // slab s ready; all warps done with the buffer being refilled

        int ns = s + NSTAGE - 1;
        if (ns < NSLAB) {
            int stn = ns % NSTAGE;
            for (int qd = tid; qd < TQ; qd += 256) {
                bool isB = qd >= AQ;
                int q2  = isB ? qd - AQ : qd;
                int row = q2 / QPR, quad = q2 % QPR;
                const float* src = (isB ? Bw + (size_t)(colBase + row) * K
                                        : A  + (size_t)(rowBase + row) * K) + ns * SLAB + quad * 4;
                uint32_t dst = smb + (isB ? BOFF + stn * BST : stn * AST) + 4u * (row * SPAD + quad * 4);
                cp16cg(dst, src);
            }
        }
        asm volatile("cp.async.commit_group;" ::: "memory");   // empty group at tail keeps accounting

        int st = s % NSTAGE;
        uint32_t ao = aFrag + st * AST;
        uint32_t bo = bFrag + st * BST;

        #pragma unroll
        for (int ks = 0; ks < SLAB; ks += 8) {
            uint32_t ua[MT][4], ub[2][4];
            #pragma unroll
            for (int mt = 0; mt < MT; mt++)
                ldsm4(ua[mt], ao + 4u * (mt * 16 * SPAD + ks));
            #pragma unroll
            for (int p = 0; p < 2; p++)
                ldsm4(ub[p], bo + 4u * (p * 16 * SPAD + ks));
            #pragma unroll
            for (int mt = 0; mt < MT; mt++) {
                #pragma unroll
                for (int p = 0; p < 2; p++) {
                    mma8(acc[mt][2 * p],     ua[mt], &ub[p][0]);
                    mma8(acc[mt][2 * p + 1], ua[mt], &ub[p][2]);
                }
            }
        }
    }

    // epilogue: c0,c1 -> (row g, col 2*t4..+1); c2,c3 -> row g+8
    #pragma unroll
    for (int mt = 0; mt < MT; mt++) {
        #pragma unroll
        for (int nt = 0; nt < 4; nt++) {
            float* cf = acc[mt][nt];
            int r  = rowBase + wRow + mt * 16 + g;
            int cc = colBase + wCol + nt * 8 + t4 * 2;
            float bx = bias[cc], by = bias[cc + 1];
            *(float2*)(C + (size_t)r * N + cc)       = make_float2(cf[0] + bx, cf[1] + by);
            *(float2*)(C + (size_t)(r + 8) * N + cc) = make_float2(cf[2] + bx, cf[3] + by);
        }
    }
}

#define GEMM_SMEM_128 (NSTAGE * (128 + BN) * SPAD * 4)   // 110592 B
#define GEMM_SMEM_64  (NSTAGE * (64 + BN) * SPAD * 4)    //  82944 B

// ---------------- sparse attention: one block per query row, one warp per head ----------------
// output written tf32-pre-rounded (consumed only by tc_gemm<1>)
__global__ __launch_bounds__(256) void sparse_attn() {
    int i = blockIdx.x;
    int h = threadIdx.x >> 5;
    int lane = threadIdx.x & 31;
    int cnt = g_cnt[i];
    if (cnt > MAXNB) cnt = MAXNB;

    __shared__ float sc[HEADS][MAXNB];
    __shared__ int   cols_s[MAXNB];
    __shared__ float wts_s[MAXNB];

    for (int t = threadIdx.x; t < cnt; t += 256) {
        cols_s[t] = g_cols[i * MAXNB + t];
        wts_s[t]  = g_wts[i * MAXNB + t];
    }
    __syncthreads();

    float2 qv = *(const float2*)(g_qkv + (size_t)i * D3 + h * HD + lane * 2);

    for (int t0 = 0; t0 < cnt; t0 += 4) {
        float d[4] = {0.f, 0.f, 0.f, 0.f};
        #pragma unroll
        for (int u = 0; u < 4; u++) {
            int t = t0 + u;
            if (t < cnt) {
                int j = cols_s[t];
                float2 kv = *(const float2*)(g_qkv + (size_t)j * D3 + Dd + h * HD + lane * 2);
                d[u] = qv.x * kv.x + qv.y * kv.y;
            }
        }
        #pragma unroll
        for (int o = 16; o; o >>= 1) {
            d[0] += __shfl_xor_sync(0xffffffffu, d[0], o);
            d[1] += __shfl_xor_sync(0xffffffffu, d[1], o);
            d[2] += __shfl_xor_sync(0xffffffffu, d[2], o);
            d[3] += __shfl_xor_sync(0xffffffffu, d[3], o);
        }
        if (lane == 0) {
            #pragma unroll
            for (int u = 0; u < 4; u++)
                if (t0 + u < cnt) sc[h][t0 + u] = d[u] * 0.125f + wts_s[t0 + u];
        }
    }
    __syncwarp();

    float m = -1e30f;
    for (int t = lane; t < cnt; t += 32) m = fmaxf(m, sc[h][t]);
    #pragma unroll
    for (int o = 16; o; o >>= 1) m = fmaxf(m, __shfl_xor_sync(0xffffffffu, m, o));

    float s = 0.0f;
    for (int t = lane; t < cnt; t += 32) {
        float e = expf(sc[h][t] - m);
        sc[h][t] = e;
        s += e;
    }
    #pragma unroll
    for (int o = 16; o; o >>= 1) s += __shfl_xor_sync(0xffffffffu, s, o);
    float inv = 1.0f / s;
    __syncwarp();

    float2 acc = make_float2(0.0f, 0.0f);
    for (int t = 0; t < cnt; t++) {
        float p = sc[h][t] * inv;
        int j = cols_s[t];
        float2 vv = *(const float2*)(g_qkv + (size_t)j * D3 + 2 * Dd + h * HD + lane * 2);
        acc.x += p * vv.x;
        acc.y += p * vv.y;
    }
    float* op = g_attn + (size_t)i * Dd + h * HD + lane * 2;
    op[0] = roundtf(acc.x);    // pre-round for tc_gemm<1>
    op[1] = roundtf(acc.y);
}

// ---------------- add + LayerNorm ----------------
// MODE 0: g_h1 = LN(x_arg + g_tmp) exact, plus g_h1r = tf32-rounded copy
// MODE 1: out_ext = LN(g_h1 + g_tmp)
template<int MODE>
__global__ __launch_bounds__(256) void add_ln(
    const float* __restrict__ a_in,
    const float* __restrict__ g, const float* __restrict__ be,
    float* __restrict__ out_ext)
{
    const float* a = (MODE == 0) ? a_in : (const float*)g_h1;
    const float* b = (const float*)g_tmp;
    float*       o = (MODE == 0) ? (float*)g_h1 : out_ext;

    int i = blockIdx.x;
    int t = threadIdx.x;
    int lane = t & 31, w = t >> 5;
    __shared__ float sh[8];

    float2 av = *(const float2*)(a + (size_t)i * Dd + t * 2);
    float2 bv = *(const float2*)(b + (size_t)i * Dd + t * 2);
    float yx = av.x + bv.x;
    float yy = av.y + bv.y;

    float s = yx + yy;
    #pragma unroll
    for (int oo = 16; oo; oo >>= 1) s += __shfl_xor_sync(0xffffffffu, s, oo);
    if (lane == 0) sh[w] = s;
    __syncthreads();
    if (t == 0) {
        float tot = 0;
        #pragma unroll
        for (int k = 0; k < 8; k++) tot += sh[k];
        sh[0] = tot;
    }
    __syncthreads();
    float mu = sh[0] * (1.0f / Dd);
    __syncthreads();

    float dx = yx - mu, dy = yy - mu;
    float qq = dx * dx + dy * dy;
    #pragma unroll
    for (int oo = 16; oo; oo >>= 1) qq += __shfl_xor_sync(0xffffffffu, qq, oo);
    if (lane == 0) sh[w] = qq;
    __syncthreads();
    if (t == 0) {
        float tot = 0;
        #pragma unroll
        for (int k = 0; k < 8; k++) tot += sh[k];
        sh[0] = tot;
    }
    __syncthreads();
    float var = sh[0] * (1.0f / Dd);
    float r = rsqrtf(var + 1e-5f);

    float2 gv  = *(const float2*)(g + t * 2);
    float2 bev = *(const float2*)(be + t * 2);
    float2 o2;
    o2.x = dx * r * gv.x + bev.x;
    o2.y = dy * r * gv.y + bev.y;
    *(float2*)(o + (size_t)i * Dd + t * 2) = o2;
    if (MODE == 0) {
        float2 o2r = make_float2(roundtf(o2.x), roundtf(o2.y));
        *(float2*)((float*)g_h1r + (size_t)i * Dd + t * 2) = o2r;
    }
}

// ---------------- launch ----------------
extern "C" void kernel_launch(void* const* d_in, const int* in_sizes, int n_in,
                              void* d_out, int out_size) {
    const float* x    = (const float*)d_in[0];
    const void*  ei   = d_in[1];
    const float* ew   = (const float*)d_in[2];
    const float* Wqkv = (const float*)d_in[3];
    const float* bqkv = (const float*)d_in[4];
    const float* Wo   = (const float*)d_in[5];
    const float* bo   = (const float*)d_in[6];
    const float* W1   = (const float*)d_in[7];
    const float* b1   = (const float*)d_in[8];
    const float* g1   = (const float*)d_in[9];
    const float* be1  = (const float*)d_in[10];
    const float* g2   = (const float*)d_in[11];
    const float* be2  = (const float*)d_in[12];
    float* out = (float*)d_out;

    cudaFuncSetAttribute((const void*)tc_gemm<0, 128>, cudaFuncAttributeMaxDynamicSharedMemorySize, GEMM_SMEM_128);
    cudaFuncSetAttribute((const void*)tc_gemm<1, 64>,  cudaFuncAttributeMaxDynamicSharedMemorySize, GEMM_SMEM_64);
    cudaFuncSetAttribute((const void*)tc_gemm<2, 64>,  cudaFuncAttributeMaxDynamicSharedMemorySize, GEMM_SMEM_64);

    // adjacency with exact last-write-wins dedup (winner grid self-restores to zero)
    k_scatter<<<Ee / 256, 256>>>(ei);
    k_append<<<Ee / 256, 256>>>(ei, ew);
    k_cleanup_diag<<<Nn / 256, 256>>>();

    // pre-round all GEMM operands to tf32 in one pass
    k_round_all<<<(R_TOT + 255) / 256, 256>>>(x, Wqkv, Wo, W1);

    // qkv = x @ Wqkv^T + bqkv            -> g_qkv      (384 CTAs, 128x128 tiles)
    tc_gemm<0, 128><<<dim3(D3 / BN, Nn / 128), 256, GEMM_SMEM_128>>>(bqkv);

    // sparse multi-head attention        -> g_attn (tf32-rounded)
    sparse_attn<<<Nn, 256>>>();

    // attn_out = g_attn @ Wo^T + bo      -> g_tmp      (256 CTAs, 64x128 tiles)
    tc_gemm<1, 64><<<dim3(Dd / BN, Nn / 64), 256, GEMM_SMEM_64>>>(bo);

    // h1 = LN(x + g_tmp)                 -> g_h1 (exact) + g_h1r (rounded)
    add_ln<0><<<Nn, 256>>>(x, g1, be1, out);

    // ffn = g_h1 @ W1^T + b1             -> g_tmp      (256 CTAs, 64x128 tiles)
    tc_gemm<2, 64><<<dim3(Dd / BN, Nn / 64), 256, GEMM_SMEM_64>>>(b1);

    // out = LN(g_h1 + g_tmp)             -> out
    add_ln<1><<<Nn, 256>>>(nullptr, g2, be2, out);
}